// round 1
// baseline (speedup 1.0000x reference)
#include <cuda_runtime.h>

#define KK 64
#define TMAX 8192

// per-batch log-likelihood scratch (no cudaMalloc allowed)
__device__ float g_ll[4096];

__device__ __forceinline__ float fast_rcp(float x) {
    float r; asm("rcp.approx.f32 %0, %1;" : "=f"(r) : "f"(x)); return r;
}

// One block per batch element. 64 threads; thread j owns state j.
// Forward recursion in scaled-exp domain:
//   u_t = (u_{t-1} . M) * exp(emit_t) / u_{t-1}[0],   C += log(u_{t-1}[0])
//   log_Z = C + log(sum_j u_T[j])
__global__ __launch_bounds__(KK) void crf_forward_kernel(
    const int* __restrict__ y, const float* __restrict__ em,
    const float* __restrict__ tr, int Tn)
{
    __shared__ __align__(16) float u_sh[2 * KK];
    __shared__ int y_sh[1024];          // T = 1024 for this problem
    __shared__ float red2[2];

    const int b = blockIdx.x;
    const int j = threadIdx.x;
    const int* yb = y + (size_t)b * Tn;
    const float* eb = em + (size_t)b * Tn * KK;

    // M column for state j, in registers: M[i] = exp(transition[i][j])
    float M[KK];
#pragma unroll
    for (int i = 0; i < KK; i++) M[i] = __expf(tr[i * KK + j]);

    // stage y row in shared
    for (int t = j; t < Tn; t += KK) y_sh[t] = yb[t];

    // alpha0 = emissions[:,0,:]  ->  u = exp(alpha0), C = 0
    u_sh[j] = __expf(eb[j]);
    float C = 0.f;
    int p = 0;
    __syncthreads();

    auto step = [&](float ecur, int tt) {
        int yt = y_sh[tt];
        if (yt != 0) {                       // uniform across block
            const float4* u4 = reinterpret_cast<const float4*>(u_sh + p * KK);
            float x0 = u_sh[p * KK];
            float a0 = 0.f, a1 = 0.f, a2 = 0.f, a3 = 0.f;
#pragma unroll
            for (int q = 0; q < KK / 4; q++) {
                float4 uu = u4[q];
                a0 = fmaf(uu.x, M[4 * q + 0], a0);
                a1 = fmaf(uu.y, M[4 * q + 1], a1);
                a2 = fmaf(uu.z, M[4 * q + 2], a2);
                a3 = fmaf(uu.w, M[4 * q + 3], a3);
            }
            float dot = (a0 + a1) + (a2 + a3);
            float x = dot * __expf(ecur) * fast_rcp(x0);
            C += __logf(x0);
            u_sh[(p ^ 1) * KK + j] = x;
            __syncthreads();
            p ^= 1;
        }
    };

    // software-pipelined emissions prefetch, depth 4
    int lim = Tn - 1;
    float e0 = eb[(size_t)min(1, lim) * KK + j];
    float e1 = eb[(size_t)min(2, lim) * KK + j];
    float e2 = eb[(size_t)min(3, lim) * KK + j];
    float e3 = eb[(size_t)min(4, lim) * KK + j];

    int t = 1;
    for (; t + 3 <= lim; t += 4) {
        int i0 = min(t + 4, lim), i1 = min(t + 5, lim);
        int i2 = min(t + 6, lim), i3 = min(t + 7, lim);
        float n0 = eb[(size_t)i0 * KK + j];
        float n1 = eb[(size_t)i1 * KK + j];
        float n2 = eb[(size_t)i2 * KK + j];
        float n3 = eb[(size_t)i3 * KK + j];
        step(e0, t); step(e1, t + 1); step(e2, t + 2); step(e3, t + 3);
        e0 = n0; e1 = n1; e2 = n2; e3 = n3;
    }
    for (; t <= lim; t++) { step(e0, t); e0 = e1; e1 = e2; e2 = e3; }

    __syncthreads();

    // log_Z = C + log(sum u)    (redundant per-thread; identical result)
    float s = 0.f;
    const float4* uf = reinterpret_cast<const float4*>(u_sh + p * KK);
#pragma unroll
    for (int q = 0; q < KK / 4; q++) {
        float4 uu = uf[q];
        s += (uu.x + uu.y) + (uu.z + uu.w);
    }
    float logz = C + __logf(s);

    // numerator: emission + transition scores along the gold path (masked)
    float num = 0.f;
    for (int tt = j; tt < Tn; tt += KK) {
        int yt = y_sh[tt];
        if (yt != 0) {
            num += eb[(size_t)tt * KK + yt];
            if (tt > 0) num += tr[y_sh[tt - 1] * KK + yt];
        }
    }
#pragma unroll
    for (int o = 16; o > 0; o >>= 1) num += __shfl_xor_sync(0xffffffffu, num, o);
    if ((j & 31) == 0) red2[j >> 5] = num;
    __syncthreads();
    if (j == 0) g_ll[b] = (red2[0] + red2[1]) - logz;
}

__global__ void crf_finalize(float* __restrict__ out, int B)
{
    __shared__ float sh[8];
    int tid = threadIdx.x;
    float v = 0.f;
    for (int i = tid; i < B; i += blockDim.x) v += g_ll[i];
#pragma unroll
    for (int o = 16; o > 0; o >>= 1) v += __shfl_xor_sync(0xffffffffu, v, o);
    if ((tid & 31) == 0) sh[tid >> 5] = v;
    __syncthreads();
    if (tid == 0) {
        float s = 0.f;
#pragma unroll
        for (int w = 0; w < 8; w++) s += sh[w];
        out[0] = -s / (float)B;
    }
}

extern "C" void kernel_launch(void* const* d_in, const int* in_sizes, int n_in,
                              void* d_out, int out_size)
{
    const int*   y  = (const int*)d_in[0];
    const float* em = (const float*)d_in[1];
    const float* tr = (const float*)d_in[2];

    const int Tn = 1024;                 // problem shape: B=256, T=1024, K=64
    const int B  = in_sizes[0] / Tn;

    crf_forward_kernel<<<B, KK>>>(y, em, tr, Tn);
    crf_finalize<<<1, 256>>>((float*)d_out, B);
}